// round 16
// baseline (speedup 1.0000x reference)
#include <cuda_runtime.h>
#include <cuda_fp16.h>
#include <math.h>
#include <stdint.h>

#define EMBED 1024
#define HEADS 16
#define HEAD_DIM 64
#define BATCH 4
#define SEQ 2048
#define FFDIM 4096
#define ROWS (BATCH * SEQ) /* 8192 */

// ---------------- scratch (device globals; allocation-free) ----------------
__device__ float g_x1[ROWS * EMBED];
__device__ __half g_h[ROWS * EMBED];     // LN1 out
__device__ __half g_y[ROWS * EMBED];     // attention out
__device__ __half g_h2[ROWS * EMBED];    // LN2 out
__device__ __half g_f[ROWS * FFDIM];     // gelu(FF1)
// attention operands: Q,K [b,h,s,d]; V transposed [b,h,d,s]
__device__ __half g_att_q[ROWS * EMBED];
__device__ __half g_att_k[ROWS * EMBED];
__device__ __half g_att_v[ROWS * EMBED];
// pre-transposed weights [N,K] fp16
__device__ __half g_wqkv[3 * EMBED * EMBED];
__device__ float  g_bqkv[3 * EMBED];
__device__ __half g_wo[EMBED * EMBED];
__device__ __half g_w1[EMBED * FFDIM];
__device__ __half g_w2[FFDIM * EMBED];

// ---------------- helpers ----------------
__device__ __forceinline__ uint32_t smem_u32(const void* p) {
    uint32_t a;
    asm("{ .reg .u64 t; cvta.to.shared.u64 t, %1; cvt.u32.u64 %0, t; }" : "=r"(a) : "l"(p));
    return a;
}
__device__ __forceinline__ uint32_t pack2_h(float a, float b) {
    __half2 H; H.x = __float2half_rn(a); H.y = __float2half_rn(b);
    return *reinterpret_cast<uint32_t*>(&H);
}
__device__ __forceinline__ float gelu_exact(float x) {
    return 0.5f * x * (1.0f + erff(x * 0.70710678118654752f));
}

#define CP_ASYNC16(dst, src) \
    asm volatile("cp.async.cg.shared.global [%0], [%1], 16;" :: "r"(dst), "l"(src))
#define CP_COMMIT()  asm volatile("cp.async.commit_group;" ::: "memory")
#define CP_WAIT(n)   asm volatile("cp.async.wait_group %0;" :: "n"(n) : "memory")

__device__ __forceinline__ void mma_f16(float* c, const uint32_t* a, const uint32_t* b) {
    asm volatile(
        "mma.sync.aligned.m16n8k16.row.col.f32.f16.f16.f32 "
        "{%0,%1,%2,%3},{%4,%5,%6,%7},{%8,%9},{%0,%1,%2,%3};"
        : "+f"(c[0]), "+f"(c[1]), "+f"(c[2]), "+f"(c[3])
        : "r"(a[0]), "r"(a[1]), "r"(a[2]), "r"(a[3]), "r"(b[0]), "r"(b[1]));
}
#define LDSM_X4(r, addr) \
    asm volatile("ldmatrix.sync.aligned.m8n8.x4.shared.b16 {%0,%1,%2,%3}, [%4];" \
                 : "=r"((r)[0]), "=r"((r)[1]), "=r"((r)[2]), "=r"((r)[3]) : "r"(addr))

// ---------------- weight transpose (fp16) ----------------
__global__ void __launch_bounds__(256) transpose_h(const float* __restrict__ W,
                                                   __half* __restrict__ Th,
                                                   int K, int N) {
    __shared__ float t[32][33];
    int n0 = blockIdx.x * 32, k0 = blockIdx.y * 32;
    int tx = threadIdx.x & 31, ty = threadIdx.x >> 5;
#pragma unroll
    for (int i = 0; i < 4; i++) {
        int k = ty + i * 8;
        t[k][tx] = W[(size_t)(k0 + k) * N + n0 + tx];
    }
    __syncthreads();
#pragma unroll
    for (int i = 0; i < 4; i++) {
        int r = ty + i * 8;
        Th[(size_t)(n0 + r) * K + k0 + tx] = __float2half_rn(t[tx][r]);
    }
}

// merged QKV transpose: z selects Wq/Wk/Wv -> g_wqkv slab
__global__ void __launch_bounds__(256) transpose_qkv(const float* __restrict__ Wq,
                                                     const float* __restrict__ Wk,
                                                     const float* __restrict__ Wv) {
    __shared__ float t[32][33];
    const float* W = (blockIdx.z == 0) ? Wq : (blockIdx.z == 1) ? Wk : Wv;
    __half* Th = g_wqkv + (size_t)blockIdx.z * EMBED * EMBED;
    int n0 = blockIdx.x * 32, k0 = blockIdx.y * 32;
    int tx = threadIdx.x & 31, ty = threadIdx.x >> 5;
#pragma unroll
    for (int i = 0; i < 4; i++) {
        int k = ty + i * 8;
        t[k][tx] = W[(size_t)(k0 + k) * EMBED + n0 + tx];
    }
    __syncthreads();
#pragma unroll
    for (int i = 0; i < 4; i++) {
        int r = ty + i * 8;
        Th[(size_t)(n0 + r) * EMBED + k0 + tx] = __float2half_rn(t[tx][r]);
    }
}

__global__ void __launch_bounds__(256) concat_bias(const float* __restrict__ bq,
                                                   const float* __restrict__ bk,
                                                   const float* __restrict__ bv) {
    int i = blockIdx.x * 256 + threadIdx.x;  // 0..1023
    g_bqkv[i]        = bq[i];
    g_bqkv[i + 1024] = bk[i];
    g_bqkv[i + 2048] = bv[i];
}

// ---------------- LayerNorm (fp16 output) ----------------
__global__ void __launch_bounds__(256) ln_kernel(const float* __restrict__ X,
                                                 const float* __restrict__ gam,
                                                 const float* __restrict__ bet,
                                                 __half* __restrict__ Y) {
    int row = blockIdx.x;
    int tid = threadIdx.x;
    const float* xr = X + (size_t)row * EMBED;
    float4 v = *reinterpret_cast<const float4*>(&xr[tid * 4]);
    float s  = v.x + v.y + v.z + v.w;
    float sq = v.x * v.x + v.y * v.y + v.z * v.z + v.w * v.w;
#pragma unroll
    for (int o = 16; o; o >>= 1) {
        s  += __shfl_xor_sync(0xffffffffu, s, o);
        sq += __shfl_xor_sync(0xffffffffu, sq, o);
    }
    __shared__ float ss[8], sqs[8];
    int w = tid >> 5;
    if ((tid & 31) == 0) { ss[w] = s; sqs[w] = sq; }
    __syncthreads();
    s = 0.f; sq = 0.f;
#pragma unroll
    for (int i = 0; i < 8; i++) { s += ss[i]; sq += sqs[i]; }
    float mu  = s * (1.0f / EMBED);
    float var = sq * (1.0f / EMBED) - mu * mu;
    float inv = rsqrtf(var + 1e-5f);
    float4 gv = *reinterpret_cast<const float4*>(&gam[tid * 4]);
    float4 bv = *reinterpret_cast<const float4*>(&bet[tid * 4]);
    float o0 = (v.x - mu) * inv * gv.x + bv.x;
    float o1 = (v.y - mu) * inv * gv.y + bv.y;
    float o2 = (v.z - mu) * inv * gv.z + bv.z;
    float o3 = (v.w - mu) * inv * gv.w + bv.w;
    size_t base = (size_t)row * EMBED + tid * 4;
    *reinterpret_cast<uint32_t*>(&Y[base])     = pack2_h(o0, o1);
    *reinterpret_cast<uint32_t*>(&Y[base + 2]) = pack2_h(o2, o3);
}

// ---------------- mma.sync GEMM (pure fp16 in, fp32 acc, 3-stage) ---------
// C = A @ B^T : A [M,K] fp16, B weights [N,K] fp16.
// EPI: 0=bias  1=bias+residual  2=bias+GELU
// OUT: 0=fp32 row-major  1=fp16 row-major  4=fused QKV
// smem per stage: A(0) B(10240), row stride 80B. 3 stages.
static constexpr int GEMM_STAGE = 20480;
static constexpr int GEMM_SMEM  = 61440;

template <int EPI, int OUT>
__device__ __forceinline__ void epi_store(float v0, float v1, int r, int c,
                                          const float* R, float* C,
                                          __half* Ch, int N) {
    if (OUT == 4) {
        // Q or K [b,h,s,d] (V handled by the smem-transpose path in the kernel)
        int kind = c >> 10;
        int c1   = c & 1023;
        size_t o2 = (((size_t)(r >> 11) * HEADS + (c1 >> 6)) * SEQ + (r & 2047)) * 64 + (c1 & 63);
        __half* dst = (kind == 0) ? g_att_q : g_att_k;
        *reinterpret_cast<uint32_t*>(&dst[o2]) = pack2_h(v0, v1);
        return;
    }
    size_t off = (size_t)r * N + c;
    if (EPI == 1) { float2 rr = *reinterpret_cast<const float2*>(&R[off]); v0 += rr.x; v1 += rr.y; }
    if (EPI == 2) { v0 = gelu_exact(v0); v1 = gelu_exact(v1); }
    if (OUT == 0) {
        float2 o; o.x = v0; o.y = v1;
        *reinterpret_cast<float2*>(&C[off]) = o;
    } else {
        *reinterpret_cast<uint32_t*>(&Ch[off]) = pack2_h(v0, v1);
    }
}

__device__ __forceinline__ void gemm_load_stage(
    uint32_t smem_base, int stage,
    const __half* A, const __half* B,
    int row0, int col0, int K, int k0, int tid) {
    uint32_t sb = smem_base + (uint32_t)stage * (uint32_t)GEMM_STAGE;
#pragma unroll
    for (int i = 0; i < 4; i++) {
        int idx = i * 256 + tid;       // 0..1023
        int arr = idx >> 9;            // 0 A, 1 B
        int pos = idx & 511;
        int r   = pos >> 2;
        int c8  = pos & 3;
        uint32_t dst = sb + (uint32_t)(arr * 10240 + r * 80 + c8 * 16);
        const __half* src = (arr == 0)
            ? &A[(size_t)(row0 + r) * K + k0 + c8 * 8]
            : &B[(size_t)(col0 + r) * K + k0 + c8 * 8];
        CP_ASYNC16(dst, src);
    }
}

template <int EPI, int OUT>
__global__ void __launch_bounds__(256, 2) gemm_mma(
    const __half* __restrict__ A, const __half* __restrict__ B,
    const float* __restrict__ bias, const float* __restrict__ R,
    float* __restrict__ C, __half* __restrict__ Ch,
    int M, int N, int K) {
    extern __shared__ char dsm[];
    const int tid  = threadIdx.x;
    const int lane = tid & 31;
    const int wid  = tid >> 5;
    const int wm   = wid & 1;
    const int wn   = wid >> 1;
    const int row0 = blockIdx.y * 128;
    const int col0 = blockIdx.x * 128;
    const uint32_t smem_base = smem_u32(dsm);

    float acc[4][4][4];
#pragma unroll
    for (int i = 0; i < 4; i++)
#pragma unroll
        for (int j = 0; j < 4; j++)
#pragma unroll
            for (int k = 0; k < 4; k++) acc[i][j][k] = 0.f;

    const int nchunks = K >> 5;
    gemm_load_stage(smem_base, 0, A, B, row0, col0, K, 0, tid);
    CP_COMMIT();
    gemm_load_stage(smem_base, 1, A, B, row0, col0, K, 32, tid);
    CP_COMMIT();

    const int tb      = lane >> 3;
    const int rb4_off = ((tb >> 1) << 3) + (lane & 7);
    const int kb4_off = (tb & 1) << 3;
    const int ra_off  = (lane & 7) + ((lane >> 3) & 1) * 8;

    int sidx = 0;
    for (int c = 0; c < nchunks; c++) {
        CP_WAIT(1);
        __syncthreads();
        // issue loads for chunk c+2 into stage (sidx+2)%3 (its readers are all
        // past this barrier), then compute chunk c — maximal overlap, 1 BAR/chunk.
        if (c + 2 < nchunks) {
            int sn = sidx + 2; if (sn >= 3) sn -= 3;
            gemm_load_stage(smem_base, sn, A, B, row0, col0, K, (c + 2) << 5, tid);
        }
        CP_COMMIT();

        uint32_t sb = smem_base + (uint32_t)sidx * (uint32_t)GEMM_STAGE;
#pragma unroll
        for (int ks = 0; ks < 32; ks += 16) {
            uint32_t bh[4][2];
#pragma unroll
            for (int np = 0; np < 2; np++) {
                int rowb = wn * 32 + np * 16 + rb4_off;
                uint32_t ab = sb + 10240u + (uint32_t)(rowb * 80 + (ks + kb4_off) * 2);
                uint32_t r4[4];
                LDSM_X4(r4, ab);
                bh[np * 2][0] = r4[0]; bh[np * 2][1] = r4[1];
                bh[np * 2 + 1][0] = r4[2]; bh[np * 2 + 1][1] = r4[3];
            }
            int ka_off = ks + ((lane >> 4) << 3);
#pragma unroll
            for (int mt = 0; mt < 4; mt++) {
                int rowa = wm * 64 + mt * 16 + ra_off;
                uint32_t aa = sb + (uint32_t)(rowa * 80 + ka_off * 2);
                uint32_t ah[4];
                LDSM_X4(ah, aa);
#pragma unroll
                for (int nt = 0; nt < 4; nt++) {
                    mma_f16(acc[mt][nt], ah, bh[nt]);
                }
            }
        }
        sidx++; if (sidx == 3) sidx = 0;
    }

    if (OUT == 4 && col0 >= 2048) {
        // ---- V epilogue: smem transpose -> coalesced [b,h,d,s] stores ----
        // stage buffer reuse: [128 cols][136 rows] halves = 34816 B
        __syncthreads();  // all warps done reading pipeline stages
        __half* st = reinterpret_cast<__half*>(dsm);
#pragma unroll
        for (int mt = 0; mt < 4; mt++) {
#pragma unroll
            for (int nt = 0; nt < 4; nt++) {
                int rl = wm * 64 + mt * 16 + (lane >> 2);
                int cl = wn * 32 + nt * 8 + (lane & 3) * 2;
                float2 b2 = *reinterpret_cast<const float2*>(&bias[col0 + cl]);
                st[(cl)     * 136 + rl]     = __float2half_rn(acc[mt][nt][0] + b2.x);
                st[(cl + 1) * 136 + rl]     = __float2half_rn(acc[mt][nt][1] + b2.y);
                st[(cl)     * 136 + rl + 8] = __float2half_rn(acc[mt][nt][2] + b2.x);
                st[(cl + 1) * 136 + rl + 8] = __float2half_rn(acc[mt][nt][3] + b2.y);
            }
        }
        __syncthreads();
        const int bq  = row0 >> 11;           // batch
        const int s0  = row0 & 2047;          // seq offset of tile
        const int cv0 = col0 - 2048;          // V-column base (0..895)
#pragma unroll
        for (int i = 0; i < 8; i++) {
            int idx = i * 256 + tid;          // 0..2047 uint4 chunks
            int cl  = idx >> 4;               // 0..127 local col
            int ch  = idx & 15;               // row chunk (8 halves)
            int c1  = cv0 + cl;
            int h   = c1 >> 6, d = c1 & 63;
            size_t dst = (((size_t)(bq * HEADS + h)) * 64 + d) * SEQ + s0 + ch * 8;
            *reinterpret_cast<uint4*>(&g_att_v[dst]) =
                *reinterpret_cast<const uint4*>(&st[cl * 136 + ch * 8]);
        }
        return;
    }

#pragma unroll
    for (int mt = 0; mt < 4; mt++) {
#pragma unroll
        for (int nt = 0; nt < 4; nt++) {
            int rg = row0 + wm * 64 + mt * 16 + (lane >> 2);
            int cg = col0 + wn * 32 + nt * 8 + (lane & 3) * 2;
            float2 b2 = *reinterpret_cast<const float2*>(&bias[cg]);
            epi_store<EPI, OUT>(acc[mt][nt][0] + b2.x, acc[mt][nt][1] + b2.y,
                                rg, cg, R, C, Ch, N);
            epi_store<EPI, OUT>(acc[mt][nt][2] + b2.x, acc[mt][nt][3] + b2.y,
                                rg + 8, cg, R, C, Ch, N);
        }
    }
}

// ---------------- tensor-core causal flash attention (fp16, 3-stage) ------
// K smem [64 keys][64 d], Vt smem [64 d][64 keys], row stride 144B.
// Q staged in stage-2 region (full 18432B), extracted to regs before mainloop.
static constexpr int AT_VOFF  = 9216;
static constexpr int AT_STAGE = 18432;
static constexpr int ATTN_SMEM = 55296;  // 3 stages
#define ATTN_SCALE 0.18033688011112042f  /* (1/8) * log2(e) */

__device__ __forceinline__ void attn_load_kv(uint32_t sb, int stage, int bh, int k0, int tid) {
    uint32_t st = sb + (uint32_t)stage * (uint32_t)AT_STAGE;
#pragma unroll
    for (int i = 0; i < 2; i++) {
        int idx = i * 256 + tid;      // 0..511
        int r   = idx >> 3;
        int c8  = idx & 7;
        uint32_t dst = st + (uint32_t)(r * 144 + c8 * 16);
        const __half* src = g_att_k + ((size_t)bh * SEQ + k0 + r) * 64 + c8 * 8;
        CP_ASYNC16(dst, src);
    }
#pragma unroll
    for (int i = 0; i < 2; i++) {
        int idx = i * 256 + tid;
        int r   = idx >> 3;
        int c8  = idx & 7;
        uint32_t dst = st + (uint32_t)(AT_VOFF + r * 144 + c8 * 16);
        const __half* src = g_att_v + ((size_t)bh * 64 + r) * SEQ + k0 + c8 * 8;
        CP_ASYNC16(dst, src);
    }
}

__global__ void __launch_bounds__(256, 2) attn_mma() {
    extern __shared__ char smbuf[];
    const int qt  = gridDim.x - 1 - blockIdx.x;   // descending work size first
    const int bh  = blockIdx.y;
    const int q0  = qt * 128;
    const int tid = threadIdx.x;
    const int lane = tid & 31;
    const int w    = tid >> 5;
    const uint32_t sb = smem_u32(smbuf);

    // ---- stage Q tile [128 x 64] into stage-2 region
#pragma unroll
    for (int i = 0; i < 4; i++) {
        int idx = i * 256 + tid;      // 0..1023
        int r   = idx >> 3;
        int c8  = idx & 7;
        uint32_t dst = sb + 2u * AT_STAGE + (uint32_t)(r * 144 + c8 * 16);
        const __half* src = g_att_q + ((size_t)bh * SEQ + q0 + r) * 64 + c8 * 8;
        CP_ASYNC16(dst, src);
    }
    CP_COMMIT();
    // ---- prologue KV loads: stages 0, 1
    attn_load_kv(sb, 0, bh, 0, tid);
    CP_COMMIT();
    const int nkt = 2 * qt + 2;
    attn_load_kv(sb, 1, bh, 64, tid);
    CP_COMMIT();

    CP_WAIT(2);                 // Q complete (KV0/KV1 may still be in flight)
    __syncthreads();
    uint32_t qh[4][4];
    {
        int ra = (lane & 7) + ((lane >> 3) & 1) * 8;
#pragma unroll
        for (int kc = 0; kc < 4; kc++) {
            int ka = kc * 16 + ((lane >> 4) << 3);
            uint32_t addr = sb + 2u * AT_STAGE + (uint32_t)((w * 16 + ra) * 144 + ka * 2);
            LDSM_X4(qh[kc], addr);
        }
    }

    float m0 = -1e30f, m1 = -1e30f, l0 = 0.f, l1 = 0.f;
    float o[8][4];
#pragma unroll
    for (int nt = 0; nt < 8; nt++)
#pragma unroll
        for (int j = 0; j < 4; j++) o[nt][j] = 0.f;

    const int tb      = lane >> 3;
    const int rk4_off = ((tb >> 1) << 3) + (lane & 7);
    const int kk4_off = (tb & 1) << 3;
    const int wrow_max = q0 + w * 16 + 15;

    int sidx = 0;
    for (int kt = 0; kt < nkt; kt++) {
        CP_WAIT(1);
        __syncthreads();
        // issue KV loads for kt+2 into stage (sidx+2)%3 (readers are past barrier;
        // stage 2 on kt=0 reuses the Q buffer — Q already extracted to registers)
        if (kt + 2 < nkt) {
            int sn = sidx + 2; if (sn >= 3) sn -= 3;
            attn_load_kv(sb, sn, bh, (kt + 2) * 64, tid);
        }
        CP_COMMIT();

        uint32_t st = sb + (uint32_t)sidx * (uint32_t)AT_STAGE;
        const int k0 = kt * 64;

        if (k0 <= wrow_max) {
            // ---- S = Q K^T
            float s[8][4];
#pragma unroll
            for (int nt = 0; nt < 8; nt++)
#pragma unroll
                for (int j = 0; j < 4; j++) s[nt][j] = 0.f;
#pragma unroll
            for (int kc = 0; kc < 4; kc++) {
#pragma unroll
                for (int np = 0; np < 4; np++) {
                    if (k0 + np * 16 > wrow_max) continue;  // fully masked -> exact skip
                    uint32_t kaddr = st + (uint32_t)((np * 16 + rk4_off) * 144 + (kc * 16 + kk4_off) * 2);
                    uint32_t kfh[4];
                    LDSM_X4(kfh, kaddr);
                    mma_f16(s[np * 2],     qh[kc], kfh);
                    mma_f16(s[np * 2 + 1], qh[kc], kfh + 2);
                }
            }

            // ---- scale (log2 domain) + causal mask
            const int r0 = q0 + w * 16 + (lane >> 2);
#pragma unroll
            for (int nt = 0; nt < 8; nt++)
#pragma unroll
                for (int j = 0; j < 4; j++) s[nt][j] *= ATTN_SCALE;
            if (k0 + 63 > q0 + w * 16) {
#pragma unroll
                for (int nt = 0; nt < 8; nt++)
#pragma unroll
                    for (int j = 0; j < 4; j++) {
                        int col = k0 + nt * 8 + (lane & 3) * 2 + (j & 1);
                        int row = r0 + ((j >> 1) << 3);
                        if (col > row) s[nt][j] = -1e30f;
                    }
            }

            // ---- online softmax in log2 domain
            float mx0 = -1e30f, mx1 = -1e30f;
#pragma unroll
            for (int nt = 0; nt < 8; nt++) {
                mx0 = fmaxf(mx0, fmaxf(s[nt][0], s[nt][1]));
                mx1 = fmaxf(mx1, fmaxf(s[nt][2], s[nt][3]));
            }
            mx0 = fmaxf(mx0, __shfl_xor_sync(0xffffffffu, mx0, 1));
            mx0 = fmaxf(mx0, __shfl_xor_sync(0xffffffffu, mx0, 2));
            mx1 = fmaxf(mx1, __shfl_xor_sync(0xffffffffu, mx1, 1));
            mx1 = fmaxf(mx1, __shfl_xor_sync(0xffffffffu, mx1, 2));
            float mn0 = fmaxf(m0, mx0), mn1 = fmaxf(m1, mx1);
            float a0 = exp2f(m0 - mn0), a1 = exp2f(m1 - mn1);
            float rl0 = 0.f, rl1 = 0.f;
#pragma unroll
            for (int nt = 0; nt < 8; nt++) {
                s[nt][0] = exp2f(s[nt][0] - mn0); rl0 += s[nt][0];
                s[nt][1] = exp2f(s[nt][1] - mn0); rl0 += s[nt][1];
                s[nt][2] = exp2f(s[nt][2] - mn1); rl1 += s[nt][2];
                s[nt][3] = exp2f(s[nt][3] - mn1); rl1 += s[nt][3];
            }
            rl0 += __shfl_xor_sync(0xffffffffu, rl0, 1);
            rl0 += __shfl_xor_sync(0xffffffffu, rl0, 2);
            rl1 += __shfl_xor_sync(0xffffffffu, rl1, 1);
            rl1 += __shfl_xor_sync(0xffffffffu, rl1, 2);
            l0 = l0 * a0 + rl0;
            l1 = l1 * a1 + rl1;
            m0 = mn0; m1 = mn1;
#pragma unroll
            for (int nt = 0; nt < 8; nt++) {
                o[nt][0] *= a0; o[nt][1] *= a0;
                o[nt][2] *= a1; o[nt][3] *= a1;
            }

            // ---- O += P V
#pragma unroll
            for (int kc = 0; kc < 4; kc++) {
                if (k0 + kc * 16 > wrow_max) continue;  // P block identically 0
                uint32_t pah[4];
                pah[0] = pack2_h(s[2 * kc][0],     s[2 * kc][1]);
                pah[1] = pack2_h(s[2 * kc][2],     s[2 * kc][3]);
                pah[2] = pack2_h(s[2 * kc + 1][0], s[2 * kc + 1][1]);
                pah[3] = pack2_h(s[2 * kc + 1][2], s[2 * kc + 1][3]);
#pragma unroll
                for (int np = 0; np < 4; np++) {
                    uint32_t vaddr = st + (uint32_t)(AT_VOFF + (np * 16 + rk4_off) * 144 + (kc * 16 + kk4_off) * 2);
                    uint32_t vfh[4];
                    LDSM_X4(vfh, vaddr);
                    mma_f16(o[np * 2],     pah, vfh);
                    mma_f16(o[np * 2 + 1], pah, vfh + 2);
                }
            }
        }
        sidx++; if (sidx == 3) sidx = 0;
    }

    // ---- write y (row-major [ROWS][EMBED] fp16)
    const float i0 = 1.f / l0, i1 = 1.f / l1;
    const int b = bh >> 4, h = bh & 15;
    const int rowg = b * SEQ + q0 + w * 16 + (lane >> 2);
#pragma unroll
    for (int nt = 0; nt < 8; nt++) {
        int colg = h * 64 + nt * 8 + (lane & 3) * 2;
        size_t off0 = (size_t)rowg * EMBED + colg;
        size_t off1 = off0 + (size_t)8 * EMBED;
        *reinterpret_cast<uint32_t*>(&g_y[off0]) = pack2_h(o[nt][0] * i0, o[nt][1] * i0);
        *reinterpret_cast<uint32_t*>(&g_y[off1]) = pack2_h(o[nt][2] * i1, o[nt][3] * i1);
    }
}

// ---------------- launch ---------------------------------------------------
extern "C" void kernel_launch(void* const* d_in, const int* in_sizes, int n_in,
                              void* d_out, int out_size) {
    const float* x     = (const float*)d_in[0];
    const float* Wq    = (const float*)d_in[1];
    const float* bq    = (const float*)d_in[2];
    const float* Wk    = (const float*)d_in[3];
    const float* bk    = (const float*)d_in[4];
    const float* Wv    = (const float*)d_in[5];
    const float* bv    = (const float*)d_in[6];
    const float* Wo    = (const float*)d_in[7];
    const float* bo    = (const float*)d_in[8];
    const float* g1    = (const float*)d_in[9];
    const float* beta1 = (const float*)d_in[10];
    const float* g2    = (const float*)d_in[11];
    const float* beta2 = (const float*)d_in[12];
    const float* W1    = (const float*)d_in[13];
    const float* b1    = (const float*)d_in[14];
    const float* W2    = (const float*)d_in[15];
    const float* b2    = (const float*)d_in[16];
    float* out = (float*)d_out;

    float* px1;
    cudaGetSymbolAddress((void**)&px1, g_x1);
    __half *ph, *py, *ph2, *pf;
    cudaGetSymbolAddress((void**)&ph,  g_h);
    cudaGetSymbolAddress((void**)&py,  g_y);
    cudaGetSymbolAddress((void**)&ph2, g_h2);
    cudaGetSymbolAddress((void**)&pf,  g_f);
    __half *wqkv, *pwo, *pw1, *pw2;
    float* pbqkv;
    cudaGetSymbolAddress((void**)&wqkv, g_wqkv);
    cudaGetSymbolAddress((void**)&pbqkv, g_bqkv);
    cudaGetSymbolAddress((void**)&pwo, g_wo);
    cudaGetSymbolAddress((void**)&pw1, g_w1);
    cudaGetSymbolAddress((void**)&pw2, g_w2);

    cudaFuncSetAttribute(gemm_mma<0, 4>, cudaFuncAttributeMaxDynamicSharedMemorySize, GEMM_SMEM);
    cudaFuncSetAttribute(gemm_mma<1, 0>, cudaFuncAttributeMaxDynamicSharedMemorySize, GEMM_SMEM);
    cudaFuncSetAttribute(gemm_mma<2, 1>, cudaFuncAttributeMaxDynamicSharedMemorySize, GEMM_SMEM);
    cudaFuncSetAttribute(attn_mma, cudaFuncAttributeMaxDynamicSharedMemorySize, ATTN_SMEM);

    dim3 t256(256);

    // ---- side stream: Wo/W1/W2 prep overlaps the LN1→QKV→attention chain ----
    cudaStream_t s2;
    cudaStreamCreateWithFlags(&s2, cudaStreamNonBlocking);
    cudaEvent_t eFork, eJoin;
    cudaEventCreateWithFlags(&eFork, cudaEventDisableTiming);
    cudaEventCreateWithFlags(&eJoin, cudaEventDisableTiming);
    cudaEventRecord(eFork, 0);
    cudaStreamWaitEvent(s2, eFork, 0);
    transpose_h<<<dim3(EMBED / 32, EMBED / 32), t256, 0, s2>>>(Wo, pwo, EMBED, EMBED);
    transpose_h<<<dim3(FFDIM / 32, EMBED / 32), t256, 0, s2>>>(W1, pw1, EMBED, FFDIM);
    transpose_h<<<dim3(EMBED / 32, FFDIM / 32), t256, 0, s2>>>(W2, pw2, FFDIM, EMBED);
    cudaEventRecord(eJoin, s2);

    // ---- main stream: QKV prep + LN1 ----
    transpose_qkv<<<dim3(EMBED / 32, EMBED / 32, 3), t256>>>(Wq, Wk, Wv);
    concat_bias<<<4, t256>>>(bq, bk, bv);
    ln_kernel<<<ROWS, t256>>>(x, g1, beta1, ph);

    // fused QKV projection (N=3072) straight into attention layouts
    dim3 gqkv(3 * EMBED / 128, ROWS / 128);
    gemm_mma<0, 4><<<gqkv, t256, GEMM_SMEM>>>(ph, wqkv, pbqkv, nullptr,
                                              nullptr, nullptr, ROWS, 3 * EMBED, EMBED);

    // tensor-core flash attention
    attn_mma<<<dim3(SEQ / 128, BATCH * HEADS), t256, ATTN_SMEM>>>();

    // join side-stream prep before Wo GEMM
    cudaStreamWaitEvent(0, eJoin, 0);

    // x1 = x + y @ Wo + bo
    dim3 g1024(EMBED / 128, ROWS / 128);
    gemm_mma<1, 0><<<g1024, t256, GEMM_SMEM>>>(py, pwo, bo, x, px1, nullptr, ROWS, EMBED, EMBED);
    // LN2
    ln_kernel<<<ROWS, t256>>>(px1, g2, beta2, ph2);
    // f = gelu(h2 @ W1 + b1)
    dim3 gff(FFDIM / 128, ROWS / 128);
    gemm_mma<2, 1><<<gff, t256, GEMM_SMEM>>>(ph2, pw1, b1, nullptr, nullptr, pf, ROWS, FFDIM, EMBED);
    // out = x1 + f @ W2 + b2
    gemm_mma<1, 0><<<g1024, t256, GEMM_SMEM>>>(pf, pw2, b2, px1, out, nullptr, ROWS, EMBED, FFDIM);
}